// round 11
// baseline (speedup 1.0000x reference)
#include <cuda_runtime.h>
#include <cuda_fp16.h>
#include <cstdint>
#include <math.h>

#define N 2048
#define K 4096
#define ROUNDS 11
#define STAGES 3
#define CHUNKS 32              // K-chunks of 128 int8 (= 128B = one SW128 row)
#define STAGE_BYTES 32768      // A 16KB + B 16KB
#define MBLKS 32
#define MTHR 512
#define NTILES 136

typedef unsigned long long ull;

// ---------------- device scratch ----------------
__device__ __half        g_Dh[(size_t)N * N];    // 8 MB fp16 distance matrix
__device__ signed char   g_Xq[(size_t)N * K];    // 8 MB int8 quantized x
__device__ int           g_sqi[N];               // int32 row norms of q
__device__ int           g_amax;                 // absmax bits (positive float)
__device__ int           g_parent[N];
__device__ int           g_root[N];
__device__ ull           g_minER[ROUNDS][N];
__device__ float         g_edgeW[N];
__device__ int           g_cnt;
__device__ unsigned      g_barCount;
__device__ volatile unsigned g_barSense;

// ---------------- helpers ----------------
__device__ __forceinline__ uint32_t s2u(const void* p) {
    return (uint32_t)__cvta_generic_to_shared(p);
}
__device__ __forceinline__ void cp16(uint32_t dst, const void* src) {
    asm volatile("cp.async.cg.shared.global [%0], [%1], 16;" :: "r"(dst), "l"(src) : "memory");
}
__device__ __forceinline__ uint32_t swz(uint32_t off) {
    return off ^ ((off >> 3) & 0x70);
}
__device__ __forceinline__ void ldmx4(uint32_t* r, uint32_t addr) {
    asm volatile("ldmatrix.sync.aligned.m8n8.x4.shared.b16 {%0,%1,%2,%3}, [%4];"
                 : "=r"(r[0]), "=r"(r[1]), "=r"(r[2]), "=r"(r[3]) : "r"(addr));
}
// int8 MMA: D(s32) += A(s8,16x32) * B(s8,32x8)
__device__ __forceinline__ void mma16832(int* d, const uint32_t* a, uint32_t b0, uint32_t b1) {
    asm volatile(
        "mma.sync.aligned.m16n8k32.row.col.s32.s8.s8.s32 "
        "{%0,%1,%2,%3}, {%4,%5,%6,%7}, {%8,%9}, {%0,%1,%2,%3};"
        : "+r"(d[0]), "+r"(d[1]), "+r"(d[2]), "+r"(d[3])
        : "r"(a[0]), "r"(a[1]), "r"(a[2]), "r"(a[3]), "r"(b0), "r"(b1));
}

__device__ __forceinline__ void gbar(unsigned* ls) {
    __threadfence();
    __syncthreads();
    if (threadIdx.x == 0) {
        unsigned s = *ls ^ 1u;
        *ls = s;
        unsigned old = atomicAdd(&g_barCount, 1u);
        if (old == MBLKS - 1) {
            g_barCount = 0;
            __threadfence();
            g_barSense = s;
        } else {
            while (g_barSense != s) __nanosleep(32);
        }
        __threadfence();
    }
    __syncthreads();
}

// ---------------- 0) absmax reduce ----------------
__global__ void amax_init_kernel() { g_amax = 0; }

__global__ void amax_kernel(const float* __restrict__ x) {
    int tid = threadIdx.x;
    size_t base = (size_t)blockIdx.x * 256 * 16 + tid * 4;
    float m = 0.f;
    #pragma unroll
    for (int it = 0; it < 4; it++) {
        float4 v = *(const float4*)(x + base + (size_t)it * 256 * 4);
        m = fmaxf(m, fmaxf(fmaxf(fabsf(v.x), fabsf(v.y)), fmaxf(fabsf(v.z), fabsf(v.w))));
    }
    for (int o = 16; o > 0; o >>= 1) m = fmaxf(m, __shfl_down_sync(0xffffffffu, m, o));
    __shared__ float wm[8];
    if ((tid & 31) == 0) wm[tid >> 5] = m;
    __syncthreads();
    if (tid == 0) {
        float t = wm[0];
        #pragma unroll
        for (int w = 1; w < 8; w++) t = fmaxf(t, wm[w]);
        atomicMax(&g_amax, __float_as_int(t));   // positive floats: int order == float order
    }
}

// ---------------- 1) quantize + int row norms ----------------
__global__ void quant_kernel(const float* __restrict__ x) {
    int row = blockIdx.x;
    int tid = threadIdx.x;
    float inv_s = 127.f / __int_as_float(g_amax);
    const float4* xr = (const float4*)(x + (size_t)row * K);
    int* qr = (int*)(g_Xq + (size_t)row * K);
    int ssum = 0;
    #pragma unroll 4
    for (int i = tid; i < K / 4; i += 256) {
        float4 v = xr[i];
        int q0 = __float2int_rn(v.x * inv_s);
        int q1 = __float2int_rn(v.y * inv_s);
        int q2 = __float2int_rn(v.z * inv_s);
        int q3 = __float2int_rn(v.w * inv_s);
        ssum += q0 * q0 + q1 * q1 + q2 * q2 + q3 * q3;
        qr[i] = (q0 & 0xff) | ((q1 & 0xff) << 8) | ((q2 & 0xff) << 16) | (q3 << 24);
    }
    for (int o = 16; o > 0; o >>= 1) ssum += __shfl_down_sync(0xffffffffu, ssum, o);
    __shared__ int ws[8];
    if ((tid & 31) == 0) ws[tid >> 5] = ssum;
    __syncthreads();
    if (tid == 0) {
        int t = 0;
        #pragma unroll
        for (int w = 0; w < 8; w++) t += ws[w];
        g_sqi[row] = t;
    }
}

// ---------------- 2) int8 IMMA GEMM + fp16 distance epilogue ----------------
// 136 linear CTAs (lower triangle); BM=BN=128, chunk=128 int8, 3-stage cp.async.
__global__ void __launch_bounds__(256, 1) gemm_dist_kernel() {
    extern __shared__ char smem[];
    int bid = blockIdx.x;
    int by = (int)((sqrtf(8.f * bid + 1.f) - 1.f) * 0.5f);
    while ((by + 1) * (by + 2) / 2 <= bid) by++;
    while (by * (by + 1) / 2 > bid) by--;
    int bx = bid - by * (by + 1) / 2;

    const int tid  = threadIdx.x;
    const int lane = tid & 31;
    const int wid  = tid >> 5;
    const int wr   = wid >> 1;
    const int wc   = wid & 1;

    uint32_t sb = s2u(smem);
    uint32_t stage_base = (sb + 1023) & ~1023u;

    __shared__ int sqi_s[128], sqj_s[128];

    const signed char* gA = g_Xq + (size_t)(by * 128) * K;
    const signed char* gB = g_Xq + (size_t)(bx * 128) * K;

    // stage: A tile 128x128B then B tile 128x128B; 8 cp16 per thread
    auto load_stage = [&](int s, int chunk) {
        uint32_t bA = stage_base + s * STAGE_BYTES;
        uint32_t bB = bA + 16384;
        size_t kb = (size_t)chunk * 128;
        #pragma unroll
        for (int it = 0; it < 4; it++) {
            int q = tid + it * 256;           // 0..1023
            int r = q >> 3, c = q & 7;
            uint32_t sw = swz((uint32_t)(r * 128 + c * 16));
            cp16(bA + sw, gA + (size_t)r * K + kb + c * 16);
            cp16(bB + sw, gB + (size_t)r * K + kb + c * 16);
        }
    };

    int acc[2][8][4];
    #pragma unroll
    for (int i = 0; i < 2; i++)
        #pragma unroll
        for (int j = 0; j < 8; j++)
            #pragma unroll
            for (int c = 0; c < 4; c++) acc[i][j][c] = 0;

    load_stage(0, 0);
    asm volatile("cp.async.commit_group;" ::: "memory");
    load_stage(1, 1);
    asm volatile("cp.async.commit_group;" ::: "memory");

    const int rowA0 = wr * 32 + (lane & 15);
    const int rowB0 = wc * 64 + (lane & 15);
    const int hb    = (lane >> 4) * 16;

    for (int c = 0; c < CHUNKS; c++) {
        int s = c % STAGES;
        asm volatile("cp.async.wait_group 1;" ::: "memory");
        __syncthreads();

        if (c + 2 < CHUNKS) load_stage((c + 2) % STAGES, c + 2);
        asm volatile("cp.async.commit_group;" ::: "memory");

        uint32_t bA = stage_base + s * STAGE_BYTES;
        uint32_t bB = bA + 16384;

        // 4 kk steps (k32 each = 32 bytes), register double-buffered
        uint32_t abuf[2][2][4], bbuf[2][4][4];
        auto addrA = [&](int kk, int mi) {
            return bA + swz((uint32_t)((rowA0 + mi * 16) * 128 + kk * 32 + hb));
        };
        auto addrB = [&](int kk, int nb) {
            return bB + swz((uint32_t)((rowB0 + nb * 16) * 128 + kk * 32 + hb));
        };
        #pragma unroll
        for (int mi = 0; mi < 2; mi++) ldmx4(abuf[0][mi], addrA(0, mi));
        #pragma unroll
        for (int nb = 0; nb < 4; nb++) ldmx4(bbuf[0][nb], addrB(0, nb));

        #pragma unroll
        for (int kk = 0; kk < 4; kk++) {
            int cur = kk & 1, nxt = cur ^ 1;
            if (kk < 3) {
                #pragma unroll
                for (int mi = 0; mi < 2; mi++) ldmx4(abuf[nxt][mi], addrA(kk + 1, mi));
                #pragma unroll
                for (int nb = 0; nb < 4; nb++) ldmx4(bbuf[nxt][nb], addrB(kk + 1, nb));
            }
            #pragma unroll
            for (int mi = 0; mi < 2; mi++)
                #pragma unroll
                for (int nb = 0; nb < 4; nb++) {
                    mma16832(acc[mi][nb * 2],     abuf[cur][mi], bbuf[cur][nb][0], bbuf[cur][nb][2]);
                    mma16832(acc[mi][nb * 2 + 1], abuf[cur][mi], bbuf[cur][nb][1], bbuf[cur][nb][3]);
                }
        }
    }

    if (tid < 128) {
        sqi_s[tid] = g_sqi[by * 128 + tid];
        sqj_s[tid] = g_sqi[bx * 128 + tid];
    }
    __syncthreads();

    float scale = __int_as_float(g_amax) * (1.f / 127.f);
    float* tbuf = (float*)(smem + (stage_base - sb));   // 128 x 129 fp32 (66KB, aliases stages)

    #pragma unroll
    for (int mi = 0; mi < 2; mi++)
        #pragma unroll
        for (int ni = 0; ni < 8; ni++)
            #pragma unroll
            for (int cc = 0; cc < 4; cc++) {
                int row = wr * 32 + mi * 16 + (lane >> 2) + ((cc >> 1) * 8);
                int col = wc * 64 + ni * 8 + (lane & 3) * 2 + (cc & 1);
                int d2 = sqi_s[row] + sqj_s[col] - 2 * acc[mi][ni][cc];   // exact, >= 0
                tbuf[row * 129 + col] = scale * sqrtf((float)max(d2, 0));
            }
    __syncthreads();

    int col = tid & 127, r0 = tid >> 7;
    for (int rr = r0; rr < 128; rr += 2)
        g_Dh[(size_t)(by * 128 + rr) * N + bx * 128 + col] = __float2half(tbuf[rr * 129 + col]);
    if (bx != by)
        for (int rr = r0; rr < 128; rr += 2)
            g_Dh[(size_t)(bx * 128 + rr) * N + by * 128 + col] = __float2half(tbuf[col * 129 + rr]);
}

// ---------------- 3) persistent Boruvka MST ----------------
__global__ void __launch_bounds__(MTHR, 1) mst_kernel() {
    __shared__ unsigned short sroot16[N];
    const int bid  = blockIdx.x;
    const int tid  = threadIdx.x;
    const int gtid = bid * MTHR + tid;
    const int lane = tid & 31;
    const int wrp  = tid >> 5;
    const int WPC  = MTHR / 32;
    const int NW   = MBLKS * WPC;

    unsigned ls = g_barSense;

    if (gtid == 0) g_cnt = 0;
    for (int i = gtid; i < N; i += MBLKS * MTHR) { g_parent[i] = i; g_root[i] = i; }
    for (int i = gtid; i < ROUNDS * N; i += MBLKS * MTHR) ((ull*)g_minER)[i] = ~0ull;
    gbar(&ls);

    for (int r = 0; r < ROUNDS; r++) {
        if (r > 0) {
            for (int j = tid; j < N; j += MTHR) {
                int p = g_parent[j];
                int pp = g_parent[p];
                while (pp != p) { p = pp; pp = g_parent[p]; }
                sroot16[j] = (unsigned short)p;
                if (bid == 0) g_root[j] = p;
            }
            __syncthreads();
        }

        for (int v = bid * WPC + wrp; v < N; v += NW) {
            int cv = (r == 0) ? v : (int)sroot16[v];
            const uint4* __restrict__ row4 = (const uint4*)(g_Dh + (size_t)v * N);
            unsigned best = 0xFFFFFFFFu;
            if (r == 0) {
                #pragma unroll 2
                for (int q = lane; q < N / 8; q += 32) {
                    uint4 dv = row4[q];
                    int j = q * 8;
                    unsigned h;
                    h = dv.x & 0xffffu;  if (j     != v) best = min(best, (h << 16) | (unsigned)(j));
                    h = dv.x >> 16;      if (j + 1 != v) best = min(best, (h << 16) | (unsigned)(j + 1));
                    h = dv.y & 0xffffu;  if (j + 2 != v) best = min(best, (h << 16) | (unsigned)(j + 2));
                    h = dv.y >> 16;      if (j + 3 != v) best = min(best, (h << 16) | (unsigned)(j + 3));
                    h = dv.z & 0xffffu;  if (j + 4 != v) best = min(best, (h << 16) | (unsigned)(j + 4));
                    h = dv.z >> 16;      if (j + 5 != v) best = min(best, (h << 16) | (unsigned)(j + 5));
                    h = dv.w & 0xffffu;  if (j + 6 != v) best = min(best, (h << 16) | (unsigned)(j + 6));
                    h = dv.w >> 16;      if (j + 7 != v) best = min(best, (h << 16) | (unsigned)(j + 7));
                }
            } else {
                const uint4* sr4 = (const uint4*)sroot16;
                #pragma unroll 2
                for (int q = lane; q < N / 8; q += 32) {
                    uint4 dv = row4[q];
                    uint4 rv = sr4[q];
                    int j = q * 8;
                    unsigned h;
                    h = dv.x & 0xffffu;  if ((int)(rv.x & 0xffffu) != cv) best = min(best, (h << 16) | (unsigned)(j));
                    h = dv.x >> 16;      if ((int)(rv.x >> 16)     != cv) best = min(best, (h << 16) | (unsigned)(j + 1));
                    h = dv.y & 0xffffu;  if ((int)(rv.y & 0xffffu) != cv) best = min(best, (h << 16) | (unsigned)(j + 2));
                    h = dv.y >> 16;      if ((int)(rv.y >> 16)     != cv) best = min(best, (h << 16) | (unsigned)(j + 3));
                    h = dv.z & 0xffffu;  if ((int)(rv.z & 0xffffu) != cv) best = min(best, (h << 16) | (unsigned)(j + 4));
                    h = dv.z >> 16;      if ((int)(rv.z >> 16)     != cv) best = min(best, (h << 16) | (unsigned)(j + 5));
                    h = dv.w & 0xffffu;  if ((int)(rv.w & 0xffffu) != cv) best = min(best, (h << 16) | (unsigned)(j + 6));
                    h = dv.w >> 16;      if ((int)(rv.w >> 16)     != cv) best = min(best, (h << 16) | (unsigned)(j + 7));
                }
            }
            #pragma unroll
            for (int o = 16; o > 0; o >>= 1)
                best = min(best, __shfl_down_sync(0xffffffffu, best, o));
            if (lane == 0 && best != 0xFFFFFFFFu) {
                __half hh = __ushort_as_half((unsigned short)(best >> 16));
                float wf = __half2float(hh);
                ull key = (((ull)__float_as_uint(wf)) << 32) |
                          (unsigned)((v << 11) | (best & 0x7FFu));
                atomicMin(&g_minER[r][cv], key);
            }
        }
        gbar(&ls);

        if (gtid < N) {
            int c = gtid;
            if (g_parent[c] == c) {
                ull key = g_minER[r][c];
                if (key != ~0ull) {
                    unsigned p = (unsigned)key;
                    int a = (p >> 11) & 2047, b = p & 2047;
                    int ra = g_root[a], rb = g_root[b];
                    int rd = (ra == c) ? rb : ra;
                    bool skip = false;
                    ull key2 = g_minER[r][rd];
                    if (key2 != ~0ull) {
                        unsigned p2 = (unsigned)key2;
                        int a2 = (p2 >> 11) & 2047, b2 = p2 & 2047;
                        int ra2 = g_root[a2], rb2 = g_root[b2];
                        int tgt = (ra2 == rd) ? rb2 : ra2;
                        if (tgt == c && c > rd) skip = true;
                    }
                    if (!skip) {
                        g_parent[c] = rd;
                        g_edgeW[atomicAdd(&g_cnt, 1)] = __uint_as_float((unsigned)(key >> 32));
                    }
                }
            }
        }
        gbar(&ls);

        int cnt = *(volatile int*)&g_cnt;
        if (cnt == N - 1) break;
    }
}

// ---------------- 4) warp-per-element rank sort ----------------
__global__ void rank_out_kernel(float* __restrict__ out) {
    __shared__ float sw[N];
    int tid  = threadIdx.x;
    int lane = tid & 31;
    int wrp  = tid >> 5;
    for (int j = tid; j < N; j += blockDim.x)
        sw[j] = (j < N - 1) ? g_edgeW[j] : 3.4028235e38f;
    __syncthreads();

    int i = blockIdx.x * 8 + wrp;
    if (i >= N - 1) return;
    float wi = sw[i];
    int rank = 0;
    const float4* sw4 = (const float4*)sw;
    #pragma unroll
    for (int q = lane; q < N / 4; q += 32) {
        float4 v = sw4[q];
        int j = q * 4;
        rank += (v.x < wi || (v.x == wi && j     < i));
        rank += (v.y < wi || (v.y == wi && j + 1 < i));
        rank += (v.z < wi || (v.z == wi && j + 2 < i));
        rank += (v.w < wi || (v.w == wi && j + 3 < i));
    }
    #pragma unroll
    for (int o = 16; o > 0; o >>= 1)
        rank += __shfl_down_sync(0xffffffffu, rank, o);
    if (lane == 0) out[rank] = wi;
}

// ---------------- launch ----------------
extern "C" void kernel_launch(void* const* d_in, const int* in_sizes, int n_in,
                              void* d_out, int out_size) {
    const float* x = (const float*)d_in[0];
    float* out = (float*)d_out;

    amax_init_kernel<<<1, 1>>>();
    amax_kernel<<<(N * K) / (256 * 16), 256>>>(x);
    quant_kernel<<<N, 256>>>(x);

    static const int SMEM_SZ = STAGES * STAGE_BYTES + 1024;   // ~97KB
    cudaFuncSetAttribute(gemm_dist_kernel,
                         cudaFuncAttributeMaxDynamicSharedMemorySize, SMEM_SZ);
    gemm_dist_kernel<<<NTILES, 256, SMEM_SZ>>>();

    mst_kernel<<<MBLKS, MTHR>>>();
    rank_out_kernel<<<256, 256>>>(out);
}

// round 12
// speedup vs baseline: 1.8089x; 1.8089x over previous
#include <cuda_runtime.h>
#include <cuda_bf16.h>
#include <cuda_fp16.h>
#include <cstdint>
#include <math.h>

#define N 2048
#define K 4096
#define ROUNDS 11
#define STAGES 3
#define CHUNKS 32              // K-chunks of 128 bf16 (two 64-wide sub-chunks)
#define STAGE_BYTES 65536
#define MBLKS 32
#define MTHR 512
#define NTILES 136

typedef unsigned long long ull;

// ---------------- device scratch ----------------
__device__ __half        g_Dh[(size_t)N * N];    // 8 MB fp16 distance matrix
__device__ __nv_bfloat16 g_Xb[(size_t)N * K];    // 16 MB
__device__ float         g_sq[N];
__device__ ull           g_minER[ROUNDS][N];
__device__ float         g_edgeW[N];
__device__ unsigned      g_barCount;
__device__ volatile unsigned g_barSense;

// ---------------- helpers ----------------
__device__ __forceinline__ uint32_t s2u(const void* p) {
    return (uint32_t)__cvta_generic_to_shared(p);
}
__device__ __forceinline__ void cp16(uint32_t dst, const void* src) {
    asm volatile("cp.async.cg.shared.global [%0], [%1], 16;" :: "r"(dst), "l"(src) : "memory");
}
__device__ __forceinline__ uint32_t swz(uint32_t off) {
    return off ^ ((off >> 3) & 0x70);
}
__device__ __forceinline__ void ldmx4(uint32_t* r, uint32_t addr) {
    asm volatile("ldmatrix.sync.aligned.m8n8.x4.shared.b16 {%0,%1,%2,%3}, [%4];"
                 : "=r"(r[0]), "=r"(r[1]), "=r"(r[2]), "=r"(r[3]) : "r"(addr));
}
__device__ __forceinline__ void mma16816(float* d, const uint32_t* a, uint32_t b0, uint32_t b1) {
    asm volatile(
        "mma.sync.aligned.m16n8k16.row.col.f32.bf16.bf16.f32 "
        "{%0,%1,%2,%3}, {%4,%5,%6,%7}, {%8,%9}, {%0,%1,%2,%3};"
        : "+f"(d[0]), "+f"(d[1]), "+f"(d[2]), "+f"(d[3])
        : "r"(a[0]), "r"(a[1]), "r"(a[2]), "r"(a[3]), "r"(b0), "r"(b1));
}

__device__ __forceinline__ void gbar(unsigned* ls) {
    __threadfence();
    __syncthreads();
    if (threadIdx.x == 0) {
        unsigned s = *ls ^ 1u;
        *ls = s;
        unsigned old = atomicAdd(&g_barCount, 1u);
        if (old == MBLKS - 1) {
            g_barCount = 0;
            __threadfence();
            g_barSense = s;
        } else {
            while (g_barSense != s) __nanosleep(32);
        }
        __threadfence();
    }
    __syncthreads();
}

// ---------------- 1) fused convert + row squared norms ----------------
__global__ void prep_kernel(const float* __restrict__ x) {
    int row = blockIdx.x;
    int tid = threadIdx.x;
    const float4* xr = (const float4*)(x + (size_t)row * K);
    __nv_bfloat16* xb = g_Xb + (size_t)row * K;
    float s = 0.f;
    #pragma unroll 4
    for (int i = tid; i < K / 4; i += 256) {
        float4 v = xr[i];
        s += v.x * v.x + v.y * v.y + v.z * v.z + v.w * v.w;
        *(__nv_bfloat162*)(xb + i * 4)     = __floats2bfloat162_rn(v.x, v.y);
        *(__nv_bfloat162*)(xb + i * 4 + 2) = __floats2bfloat162_rn(v.z, v.w);
    }
    for (int o = 16; o > 0; o >>= 1) s += __shfl_down_sync(0xffffffffu, s, o);
    __shared__ float ws[8];
    if ((tid & 31) == 0) ws[tid >> 5] = s;
    __syncthreads();
    if (tid == 0) {
        float t = 0.f;
        #pragma unroll
        for (int w = 0; w < 8; w++) t += ws[w];
        g_sq[row] = t;
    }
}

// ---------------- 2) bf16 HMMA GEMM + fp16 distance epilogue ----------------
__global__ void __launch_bounds__(256, 1) gemm_dist_kernel() {
    extern __shared__ char smem[];
    int bid = blockIdx.x;
    int by = (int)((sqrtf(8.f * bid + 1.f) - 1.f) * 0.5f);
    while ((by + 1) * (by + 2) / 2 <= bid) by++;
    while (by * (by + 1) / 2 > bid) by--;
    int bx = bid - by * (by + 1) / 2;

    const int tid  = threadIdx.x;
    const int wid  = tid >> 5;
    const int lane = tid & 31;
    const int wr   = wid >> 1;
    const int wc   = wid & 1;

    uint32_t sb = s2u(smem);
    uint32_t stage_base = (sb + 1023) & ~1023u;

    __shared__ float sqi_s[128], sqj_s[128];

    const __nv_bfloat16* gA = g_Xb + (size_t)(by * 128) * K;
    const __nv_bfloat16* gB = g_Xb + (size_t)(bx * 128) * K;

    auto load_stage = [&](int s, int chunk) {
        #pragma unroll
        for (int h = 0; h < 2; h++) {
            uint32_t bA = stage_base + s * STAGE_BYTES + h * 32768;
            uint32_t bB = bA + 16384;
            size_t kb = ((size_t)chunk * 2 + h) * 128;
            #pragma unroll
            for (int it = 0; it < 4; it++) {
                int q = tid + it * 256;
                int r = q >> 3, c = q & 7;
                uint32_t sw = swz((uint32_t)(r * 128 + c * 16));
                cp16(bA + sw, (const char*)(gA + (size_t)r * K) + kb + c * 16);
                cp16(bB + sw, (const char*)(gB + (size_t)r * K) + kb + c * 16);
            }
        }
    };

    float acc[2][8][4];
    #pragma unroll
    for (int i = 0; i < 2; i++)
        #pragma unroll
        for (int j = 0; j < 8; j++)
            #pragma unroll
            for (int c = 0; c < 4; c++) acc[i][j][c] = 0.f;

    load_stage(0, 0);
    asm volatile("cp.async.commit_group;" ::: "memory");
    load_stage(1, 1);
    asm volatile("cp.async.commit_group;" ::: "memory");

    const int rowA0 = wr * 32 + (lane & 15);
    const int rowB0 = wc * 64 + (lane & 15);
    const int hb    = (lane >> 4) * 16;

    for (int c = 0; c < CHUNKS; c++) {
        int s = c % STAGES;
        asm volatile("cp.async.wait_group 1;" ::: "memory");
        __syncthreads();

        if (c + 2 < CHUNKS) load_stage((c + 2) % STAGES, c + 2);
        asm volatile("cp.async.commit_group;" ::: "memory");

        uint32_t base = stage_base + s * STAGE_BYTES;

        uint32_t abuf[2][2][4], bbuf[2][4][4];
        auto addrA = [&](int kk, int mi) {
            return base + (kk >> 2) * 32768 +
                   swz((uint32_t)((rowA0 + mi * 16) * 128 + (kk & 3) * 32 + hb));
        };
        auto addrB = [&](int kk, int nb) {
            return base + (kk >> 2) * 32768 + 16384 +
                   swz((uint32_t)((rowB0 + nb * 16) * 128 + (kk & 3) * 32 + hb));
        };
        #pragma unroll
        for (int mi = 0; mi < 2; mi++) ldmx4(abuf[0][mi], addrA(0, mi));
        #pragma unroll
        for (int nb = 0; nb < 4; nb++) ldmx4(bbuf[0][nb], addrB(0, nb));

        #pragma unroll
        for (int kk = 0; kk < 8; kk++) {
            int cur = kk & 1, nxt = cur ^ 1;
            if (kk < 7) {
                #pragma unroll
                for (int mi = 0; mi < 2; mi++) ldmx4(abuf[nxt][mi], addrA(kk + 1, mi));
                #pragma unroll
                for (int nb = 0; nb < 4; nb++) ldmx4(bbuf[nxt][nb], addrB(kk + 1, nb));
            }
            #pragma unroll
            for (int mi = 0; mi < 2; mi++)
                #pragma unroll
                for (int nb = 0; nb < 4; nb++) {
                    mma16816(acc[mi][nb * 2],     abuf[cur][mi], bbuf[cur][nb][0], bbuf[cur][nb][2]);
                    mma16816(acc[mi][nb * 2 + 1], abuf[cur][mi], bbuf[cur][nb][1], bbuf[cur][nb][3]);
                }
        }
    }

    if (tid < 128) {
        sqi_s[tid] = g_sq[by * 128 + tid];
        sqj_s[tid] = g_sq[bx * 128 + tid];
    }
    __syncthreads();

    float* tbuf = (float*)(smem + (stage_base - sb));   // 128 x 129 fp32

    #pragma unroll
    for (int mi = 0; mi < 2; mi++)
        #pragma unroll
        for (int ni = 0; ni < 8; ni++)
            #pragma unroll
            for (int cc = 0; cc < 4; cc++) {
                int row = wr * 32 + mi * 16 + (lane >> 2) + ((cc >> 1) * 8);
                int col = wc * 64 + ni * 8 + (lane & 3) * 2 + (cc & 1);
                float d2 = sqi_s[row] + sqj_s[col] - 2.f * acc[mi][ni][cc];
                tbuf[row * 129 + col] = sqrtf(fmaxf(d2, 0.f));
            }
    __syncthreads();

    int col = tid & 127, r0 = tid >> 7;
    for (int rr = r0; rr < 128; rr += 2)
        g_Dh[(size_t)(by * 128 + rr) * N + bx * 128 + col] = __float2half(tbuf[rr * 129 + col]);
    if (bx != by)
        for (int rr = r0; rr < 128; rr += 2)
            g_Dh[(size_t)(bx * 128 + rr) * N + by * 128 + col] = __float2half(tbuf[col * 129 + rr]);
}

// ---------------- 3) persistent Boruvka MST, replicated union-find ----------------
// One grid barrier per round: scan(atomicMin g_minER[r]) -> gbar -> local merge.
__global__ void __launch_bounds__(MTHR, 1) mst_kernel() {
    __shared__ unsigned short parent16[N];   // per-CTA replicated parent (4KB)
    __shared__ unsigned short sroot16[N];    // roots snapshot (4KB)
    __shared__ int scnt;                     // cumulative merge count (identical across CTAs)
    const int bid  = blockIdx.x;
    const int tid  = threadIdx.x;
    const int gtid = bid * MTHR + tid;
    const int lane = tid & 31;
    const int wrp  = tid >> 5;
    const int WPC  = MTHR / 32;
    const int NW   = MBLKS * WPC;

    unsigned ls = g_barSense;

    for (int i = gtid; i < ROUNDS * N; i += MBLKS * MTHR) ((ull*)g_minER)[i] = ~0ull;
    for (int j = tid; j < N; j += MTHR) parent16[j] = (unsigned short)j;
    if (tid == 0) scnt = 0;
    gbar(&ls);   // minER init visible before any scan

    for (int r = 0; r < ROUNDS; r++) {
        if (r > 0) {
            // local root computation from replicated parent
            for (int j = tid; j < N; j += MTHR) {
                int p = parent16[j];
                int pp = parent16[p];
                while (pp != p) { p = pp; pp = parent16[p]; }
                sroot16[j] = (unsigned short)p;
            }
            __syncthreads();
        }

        // warp-per-vertex scan of fp16 rows
        for (int v = bid * WPC + wrp; v < N; v += NW) {
            int cv = (r == 0) ? v : (int)sroot16[v];
            const uint4* __restrict__ row4 = (const uint4*)(g_Dh + (size_t)v * N);
            unsigned best = 0xFFFFFFFFu;
            if (r == 0) {
                #pragma unroll 2
                for (int q = lane; q < N / 8; q += 32) {
                    uint4 dv = row4[q];
                    int j = q * 8;
                    unsigned h;
                    h = dv.x & 0xffffu;  if (j     != v) best = min(best, (h << 16) | (unsigned)(j));
                    h = dv.x >> 16;      if (j + 1 != v) best = min(best, (h << 16) | (unsigned)(j + 1));
                    h = dv.y & 0xffffu;  if (j + 2 != v) best = min(best, (h << 16) | (unsigned)(j + 2));
                    h = dv.y >> 16;      if (j + 3 != v) best = min(best, (h << 16) | (unsigned)(j + 3));
                    h = dv.z & 0xffffu;  if (j + 4 != v) best = min(best, (h << 16) | (unsigned)(j + 4));
                    h = dv.z >> 16;      if (j + 5 != v) best = min(best, (h << 16) | (unsigned)(j + 5));
                    h = dv.w & 0xffffu;  if (j + 6 != v) best = min(best, (h << 16) | (unsigned)(j + 6));
                    h = dv.w >> 16;      if (j + 7 != v) best = min(best, (h << 16) | (unsigned)(j + 7));
                }
            } else {
                const uint4* sr4 = (const uint4*)sroot16;
                #pragma unroll 2
                for (int q = lane; q < N / 8; q += 32) {
                    uint4 dv = row4[q];
                    uint4 rv = sr4[q];
                    int j = q * 8;
                    unsigned h;
                    h = dv.x & 0xffffu;  if ((int)(rv.x & 0xffffu) != cv) best = min(best, (h << 16) | (unsigned)(j));
                    h = dv.x >> 16;      if ((int)(rv.x >> 16)     != cv) best = min(best, (h << 16) | (unsigned)(j + 1));
                    h = dv.y & 0xffffu;  if ((int)(rv.y & 0xffffu) != cv) best = min(best, (h << 16) | (unsigned)(j + 2));
                    h = dv.y >> 16;      if ((int)(rv.y >> 16)     != cv) best = min(best, (h << 16) | (unsigned)(j + 3));
                    h = dv.z & 0xffffu;  if ((int)(rv.z & 0xffffu) != cv) best = min(best, (h << 16) | (unsigned)(j + 4));
                    h = dv.z >> 16;      if ((int)(rv.z >> 16)     != cv) best = min(best, (h << 16) | (unsigned)(j + 5));
                    h = dv.w & 0xffffu;  if ((int)(rv.w & 0xffffu) != cv) best = min(best, (h << 16) | (unsigned)(j + 6));
                    h = dv.w >> 16;      if ((int)(rv.w >> 16)     != cv) best = min(best, (h << 16) | (unsigned)(j + 7));
                }
            }
            #pragma unroll
            for (int o = 16; o > 0; o >>= 1)
                best = min(best, __shfl_down_sync(0xffffffffu, best, o));
            if (lane == 0 && best != 0xFFFFFFFFu) {
                __half hh = __ushort_as_half((unsigned short)(best >> 16));
                float wf = __half2float(hh);
                ull key = (((ull)__float_as_uint(wf)) << 32) |
                          (unsigned)((v << 11) | (best & 0x7FFu));
                atomicMin(&g_minER[r][cv], key);
            }
        }
        gbar(&ls);   // the ONLY grid barrier per round

        // redundant merge in every CTA on the replicated parent
        for (int c = tid; c < N; c += MTHR) {
            if ((int)parent16[c] != c) continue;
            ull key = g_minER[r][c];
            if (key == ~0ull) continue;
            unsigned p = (unsigned)key;
            int a = (p >> 11) & 2047, b = p & 2047;
            int ra = (r == 0) ? a : (int)sroot16[a];
            int rb = (r == 0) ? b : (int)sroot16[b];
            int rd = (ra == c) ? rb : ra;
            bool skip = false;
            ull key2 = g_minER[r][rd];
            if (key2 != ~0ull) {
                unsigned p2 = (unsigned)key2;
                int a2 = (p2 >> 11) & 2047, b2 = p2 & 2047;
                int ra2 = (r == 0) ? a2 : (int)sroot16[a2];
                int rb2 = (r == 0) ? b2 : (int)sroot16[b2];
                int tgt = (ra2 == rd) ? rb2 : ra2;
                if (tgt == c && c > rd) skip = true;
            }
            if (!skip) {
                parent16[c] = (unsigned short)rd;
                int idx = atomicAdd(&scnt, 1);
                if (bid == 0)
                    g_edgeW[idx] = __uint_as_float((unsigned)(key >> 32));
            }
        }
        __syncthreads();
        if (scnt == N - 1) break;   // identical in all CTAs -> uniform exit
    }
}

// ---------------- 4) warp-per-element rank sort ----------------
__global__ void rank_out_kernel(float* __restrict__ out) {
    __shared__ float sw[N];
    int tid  = threadIdx.x;
    int lane = tid & 31;
    int wrp  = tid >> 5;
    for (int j = tid; j < N; j += blockDim.x)
        sw[j] = (j < N - 1) ? g_edgeW[j] : 3.4028235e38f;
    __syncthreads();

    int i = blockIdx.x * 8 + wrp;
    if (i >= N - 1) return;
    float wi = sw[i];
    int rank = 0;
    const float4* sw4 = (const float4*)sw;
    #pragma unroll
    for (int q = lane; q < N / 4; q += 32) {
        float4 v = sw4[q];
        int j = q * 4;
        rank += (v.x < wi || (v.x == wi && j     < i));
        rank += (v.y < wi || (v.y == wi && j + 1 < i));
        rank += (v.z < wi || (v.z == wi && j + 2 < i));
        rank += (v.w < wi || (v.w == wi && j + 3 < i));
    }
    #pragma unroll
    for (int o = 16; o > 0; o >>= 1)
        rank += __shfl_down_sync(0xffffffffu, rank, o);
    if (lane == 0) out[rank] = wi;
}

// ---------------- launch ----------------
extern "C" void kernel_launch(void* const* d_in, const int* in_sizes, int n_in,
                              void* d_out, int out_size) {
    const float* x = (const float*)d_in[0];
    float* out = (float*)d_out;

    prep_kernel<<<N, 256>>>(x);

    static const int SMEM_SZ = STAGES * STAGE_BYTES + 1024;   // ~197KB
    cudaFuncSetAttribute(gemm_dist_kernel,
                         cudaFuncAttributeMaxDynamicSharedMemorySize, SMEM_SZ);
    gemm_dist_kernel<<<NTILES, 256, SMEM_SZ>>>();

    mst_kernel<<<MBLKS, MTHR>>>();
    rank_out_kernel<<<256, 256>>>(out);
}

// round 13
// speedup vs baseline: 1.9089x; 1.0553x over previous
#include <cuda_runtime.h>
#include <cuda_fp16.h>
#include <cstdint>
#include <math.h>

#define N 2048
#define K 4096
#define ROUNDS 11
#define STAGES 3
#define CHUNKS 32              // K-chunks of 128 fp16 (two 64-wide sub-chunks)
#define STAGE_BYTES 65536
#define MBLKS 32
#define MTHR 512
#define NTILES 136

typedef unsigned long long ull;

// ---------------- device scratch ----------------
__device__ __half        g_Dh[(size_t)N * N];    // 8 MB fp16 distance matrix
__device__ __half        g_Xh[(size_t)N * K];    // 16 MB fp16 copy of x
__device__ float         g_sq[N];
__device__ unsigned      g_min0[N];              // round-0 per-vertex best (h16<<16|j)
__device__ ull           g_minER[ROUNDS][N];
__device__ float         g_edgeW[N];
__device__ unsigned      g_barCount;
__device__ volatile unsigned g_barSense;

// ---------------- helpers ----------------
__device__ __forceinline__ uint32_t s2u(const void* p) {
    return (uint32_t)__cvta_generic_to_shared(p);
}
__device__ __forceinline__ void cp16(uint32_t dst, const void* src) {
    asm volatile("cp.async.cg.shared.global [%0], [%1], 16;" :: "r"(dst), "l"(src) : "memory");
}
__device__ __forceinline__ uint32_t swz(uint32_t off) {
    return off ^ ((off >> 3) & 0x70);
}
__device__ __forceinline__ void ldmx4(uint32_t* r, uint32_t addr) {
    asm volatile("ldmatrix.sync.aligned.m8n8.x4.shared.b16 {%0,%1,%2,%3}, [%4];"
                 : "=r"(r[0]), "=r"(r[1]), "=r"(r[2]), "=r"(r[3]) : "r"(addr));
}
// fp16-accumulate HMMA: D(f16x2 in 2 regs) += A(f16) * B(f16)
__device__ __forceinline__ void mma16816h(uint32_t* d, const uint32_t* a, uint32_t b0, uint32_t b1) {
    asm volatile(
        "mma.sync.aligned.m16n8k16.row.col.f16.f16.f16.f16 "
        "{%0,%1}, {%2,%3,%4,%5}, {%6,%7}, {%0,%1};"
        : "+r"(d[0]), "+r"(d[1])
        : "r"(a[0]), "r"(a[1]), "r"(a[2]), "r"(a[3]), "r"(b0), "r"(b1));
}

__device__ __forceinline__ void gbar(unsigned* ls) {
    __threadfence();
    __syncthreads();
    if (threadIdx.x == 0) {
        unsigned s = *ls ^ 1u;
        *ls = s;
        unsigned old = atomicAdd(&g_barCount, 1u);
        if (old == MBLKS - 1) {
            g_barCount = 0;
            __threadfence();
            g_barSense = s;
        } else {
            while (g_barSense != s) __nanosleep(32);
        }
        __threadfence();
    }
    __syncthreads();
}

// ---------------- 1) fused convert(fp16) + row squared norms + g_min0 init ----------------
__global__ void prep_kernel(const float* __restrict__ x) {
    int row = blockIdx.x;
    int tid = threadIdx.x;
    const float4* xr = (const float4*)(x + (size_t)row * K);
    __half* xb = g_Xh + (size_t)row * K;
    float s = 0.f;
    #pragma unroll 4
    for (int i = tid; i < K / 4; i += 256) {
        float4 v = xr[i];
        s += v.x * v.x + v.y * v.y + v.z * v.z + v.w * v.w;
        *(__half2*)(xb + i * 4)     = __floats2half2_rn(v.x, v.y);
        *(__half2*)(xb + i * 4 + 2) = __floats2half2_rn(v.z, v.w);
    }
    for (int o = 16; o > 0; o >>= 1) s += __shfl_down_sync(0xffffffffu, s, o);
    __shared__ float ws[8];
    if ((tid & 31) == 0) ws[tid >> 5] = s;
    __syncthreads();
    if (tid == 0) {
        float t = 0.f;
        #pragma unroll
        for (int w = 0; w < 8; w++) t += ws[w];
        g_sq[row] = t;
        g_min0[row] = 0xFFFFFFFFu;
    }
}

// ---------------- 2) fp16 HMMA GEMM (f16 accum, chunk-promoted) + epilogue ----------------
__global__ void __launch_bounds__(256, 1) gemm_dist_kernel() {
    extern __shared__ char smem[];
    int bid = blockIdx.x;
    int by = (int)((sqrtf(8.f * bid + 1.f) - 1.f) * 0.5f);
    while ((by + 1) * (by + 2) / 2 <= bid) by++;
    while (by * (by + 1) / 2 > bid) by--;
    int bx = bid - by * (by + 1) / 2;

    const int tid  = threadIdx.x;
    const int wid  = tid >> 5;
    const int lane = tid & 31;
    const int wr   = wid >> 1;
    const int wc   = wid & 1;

    uint32_t sb = s2u(smem);
    uint32_t stage_base = (sb + 1023) & ~1023u;

    __shared__ float sqi_s[128], sqj_s[128];

    const __half* gA = g_Xh + (size_t)(by * 128) * K;
    const __half* gB = g_Xh + (size_t)(bx * 128) * K;

    auto load_stage = [&](int s, int chunk) {
        #pragma unroll
        for (int h = 0; h < 2; h++) {
            uint32_t bA = stage_base + s * STAGE_BYTES + h * 32768;
            uint32_t bB = bA + 16384;
            size_t kb = ((size_t)chunk * 2 + h) * 128;
            #pragma unroll
            for (int it = 0; it < 4; it++) {
                int q = tid + it * 256;
                int r = q >> 3, c = q & 7;
                uint32_t sw = swz((uint32_t)(r * 128 + c * 16));
                cp16(bA + sw, (const char*)(gA + (size_t)r * K) + kb + c * 16);
                cp16(bB + sw, (const char*)(gB + (size_t)r * K) + kb + c * 16);
            }
        }
    };

    float acc[2][8][4];
    #pragma unroll
    for (int i = 0; i < 2; i++)
        #pragma unroll
        for (int j = 0; j < 8; j++)
            #pragma unroll
            for (int c = 0; c < 4; c++) acc[i][j][c] = 0.f;

    load_stage(0, 0);
    asm volatile("cp.async.commit_group;" ::: "memory");
    load_stage(1, 1);
    asm volatile("cp.async.commit_group;" ::: "memory");

    const int rowA0 = wr * 32 + (lane & 15);
    const int rowB0 = wc * 64 + (lane & 15);
    const int hb    = (lane >> 4) * 16;

    for (int c = 0; c < CHUNKS; c++) {
        int s = c % STAGES;
        asm volatile("cp.async.wait_group 1;" ::: "memory");
        __syncthreads();

        if (c + 2 < CHUNKS) load_stage((c + 2) % STAGES, c + 2);
        asm volatile("cp.async.commit_group;" ::: "memory");

        uint32_t base = stage_base + s * STAGE_BYTES;

        // fp16 accumulators for this chunk
        uint32_t acc16[2][8][2];
        #pragma unroll
        for (int mi = 0; mi < 2; mi++)
            #pragma unroll
            for (int ni = 0; ni < 8; ni++) { acc16[mi][ni][0] = 0; acc16[mi][ni][1] = 0; }

        uint32_t abuf[2][2][4], bbuf[2][4][4];
        auto addrA = [&](int kk, int mi) {
            return base + (kk >> 2) * 32768 +
                   swz((uint32_t)((rowA0 + mi * 16) * 128 + (kk & 3) * 32 + hb));
        };
        auto addrB = [&](int kk, int nb) {
            return base + (kk >> 2) * 32768 + 16384 +
                   swz((uint32_t)((rowB0 + nb * 16) * 128 + (kk & 3) * 32 + hb));
        };
        #pragma unroll
        for (int mi = 0; mi < 2; mi++) ldmx4(abuf[0][mi], addrA(0, mi));
        #pragma unroll
        for (int nb = 0; nb < 4; nb++) ldmx4(bbuf[0][nb], addrB(0, nb));

        #pragma unroll
        for (int kk = 0; kk < 8; kk++) {
            int cur = kk & 1, nxt = cur ^ 1;
            if (kk < 7) {
                #pragma unroll
                for (int mi = 0; mi < 2; mi++) ldmx4(abuf[nxt][mi], addrA(kk + 1, mi));
                #pragma unroll
                for (int nb = 0; nb < 4; nb++) ldmx4(bbuf[nxt][nb], addrB(kk + 1, nb));
            }
            #pragma unroll
            for (int mi = 0; mi < 2; mi++)
                #pragma unroll
                for (int nb = 0; nb < 4; nb++) {
                    mma16816h(acc16[mi][nb * 2],     abuf[cur][mi], bbuf[cur][nb][0], bbuf[cur][nb][2]);
                    mma16816h(acc16[mi][nb * 2 + 1], abuf[cur][mi], bbuf[cur][nb][1], bbuf[cur][nb][3]);
                }
        }

        // promote chunk partials to fp32
        #pragma unroll
        for (int mi = 0; mi < 2; mi++)
            #pragma unroll
            for (int ni = 0; ni < 8; ni++) {
                float2 f0 = __half22float2(*(__half2*)&acc16[mi][ni][0]);
                float2 f1 = __half22float2(*(__half2*)&acc16[mi][ni][1]);
                acc[mi][ni][0] += f0.x; acc[mi][ni][1] += f0.y;
                acc[mi][ni][2] += f1.x; acc[mi][ni][3] += f1.y;
            }
    }

    if (tid < 128) {
        sqi_s[tid] = g_sq[by * 128 + tid];
        sqj_s[tid] = g_sq[bx * 128 + tid];
    }
    __syncthreads();

    float* tbuf = (float*)(smem + (stage_base - sb));   // 128 x 129 fp32

    #pragma unroll
    for (int mi = 0; mi < 2; mi++)
        #pragma unroll
        for (int ni = 0; ni < 8; ni++)
            #pragma unroll
            for (int cc = 0; cc < 4; cc++) {
                int row = wr * 32 + mi * 16 + (lane >> 2) + ((cc >> 1) * 8);
                int col = wc * 64 + ni * 8 + (lane & 3) * 2 + (cc & 1);
                float d2 = sqi_s[row] + sqj_s[col] - 2.f * acc[mi][ni][cc];
                tbuf[row * 129 + col] = sqrtf(fmaxf(d2, 0.f));
            }
    __syncthreads();

    // global writes
    int col = tid & 127, r0 = tid >> 7;
    for (int rr = r0; rr < 128; rr += 2)
        g_Dh[(size_t)(by * 128 + rr) * N + bx * 128 + col] = __float2half(tbuf[rr * 129 + col]);
    if (bx != by)
        for (int rr = r0; rr < 128; rr += 2)
            g_Dh[(size_t)(bx * 128 + rr) * N + by * 128 + col] = __float2half(tbuf[col * 129 + rr]);

    // fused MST round-0 row minima (same fp16 values + tie-break as a scan of g_Dh)
    if (tid < 128) {
        int gv = by * 128 + tid;
        unsigned best = 0xFFFFFFFFu;
        #pragma unroll 4
        for (int cc = 0; cc < 128; cc++) {
            if (bx == by && cc == tid) continue;
            unsigned short h = __half_as_ushort(__float2half(tbuf[tid * 129 + cc]));
            best = min(best, ((unsigned)h << 16) | (unsigned)(bx * 128 + cc));
        }
        atomicMin(&g_min0[gv], best);
    } else if (bx != by) {
        int rr = tid - 128;
        int gv = bx * 128 + rr;
        unsigned best = 0xFFFFFFFFu;
        #pragma unroll 4
        for (int cc = 0; cc < 128; cc++) {
            unsigned short h = __half_as_ushort(__float2half(tbuf[cc * 129 + rr]));
            best = min(best, ((unsigned)h << 16) | (unsigned)(by * 128 + cc));
        }
        atomicMin(&g_min0[gv], best);
    }
}

// ---------------- 3) persistent Boruvka MST, replicated union-find ----------------
// Round 0 merges straight from g_min0 (computed by GEMM); rounds >=1 scan g_Dh.
__global__ void __launch_bounds__(MTHR, 1) mst_kernel() {
    __shared__ unsigned short parent16[N];
    __shared__ unsigned short sroot16[N];
    __shared__ int scnt;
    const int bid  = blockIdx.x;
    const int tid  = threadIdx.x;
    const int gtid = bid * MTHR + tid;
    const int lane = tid & 31;
    const int wrp  = tid >> 5;
    const int WPC  = MTHR / 32;
    const int NW   = MBLKS * WPC;

    unsigned ls = g_barSense;

    for (int i = gtid; i < ROUNDS * N; i += MBLKS * MTHR) ((ull*)g_minER)[i] = ~0ull;
    for (int j = tid; j < N; j += MTHR) parent16[j] = (unsigned short)j;
    if (tid == 0) scnt = 0;
    gbar(&ls);   // minER init visible before any round>=1 scan

    for (int r = 0; r < ROUNDS; r++) {
        if (r > 0) {
            for (int j = tid; j < N; j += MTHR) {
                int p = parent16[j];
                int pp = parent16[p];
                while (pp != p) { p = pp; pp = parent16[p]; }
                sroot16[j] = (unsigned short)p;
            }
            __syncthreads();

            for (int v = bid * WPC + wrp; v < N; v += NW) {
                int cv = (int)sroot16[v];
                const uint4* __restrict__ row4 = (const uint4*)(g_Dh + (size_t)v * N);
                const uint4* sr4 = (const uint4*)sroot16;
                unsigned best = 0xFFFFFFFFu;
                #pragma unroll 2
                for (int q = lane; q < N / 8; q += 32) {
                    uint4 dv = row4[q];
                    uint4 rv = sr4[q];
                    int j = q * 8;
                    unsigned h;
                    h = dv.x & 0xffffu;  if ((int)(rv.x & 0xffffu) != cv) best = min(best, (h << 16) | (unsigned)(j));
                    h = dv.x >> 16;      if ((int)(rv.x >> 16)     != cv) best = min(best, (h << 16) | (unsigned)(j + 1));
                    h = dv.y & 0xffffu;  if ((int)(rv.y & 0xffffu) != cv) best = min(best, (h << 16) | (unsigned)(j + 2));
                    h = dv.y >> 16;      if ((int)(rv.y >> 16)     != cv) best = min(best, (h << 16) | (unsigned)(j + 3));
                    h = dv.z & 0xffffu;  if ((int)(rv.z & 0xffffu) != cv) best = min(best, (h << 16) | (unsigned)(j + 4));
                    h = dv.z >> 16;      if ((int)(rv.z >> 16)     != cv) best = min(best, (h << 16) | (unsigned)(j + 5));
                    h = dv.w & 0xffffu;  if ((int)(rv.w & 0xffffu) != cv) best = min(best, (h << 16) | (unsigned)(j + 6));
                    h = dv.w >> 16;      if ((int)(rv.w >> 16)     != cv) best = min(best, (h << 16) | (unsigned)(j + 7));
                }
                #pragma unroll
                for (int o = 16; o > 0; o >>= 1)
                    best = min(best, __shfl_down_sync(0xffffffffu, best, o));
                if (lane == 0 && best != 0xFFFFFFFFu) {
                    float wf = __half2float(__ushort_as_half((unsigned short)(best >> 16)));
                    ull key = (((ull)__float_as_uint(wf)) << 32) |
                              (unsigned)((v << 11) | (best & 0x7FFu));
                    atomicMin(&g_minER[r][cv], key);
                }
            }
            gbar(&ls);
        }

        // redundant merge in every CTA on the replicated parent
        for (int c = tid; c < N; c += MTHR) {
            if ((int)parent16[c] != c) continue;
            int rd;
            float wf;
            if (r == 0) {
                unsigned k32 = g_min0[c];
                int b = (int)(k32 & 0x7FFu);
                rd = b;                                     // all singletons in round 0
                unsigned k32r = g_min0[rd];
                int tgt = (int)(k32r & 0x7FFu);
                if (tgt == c && c > rd) continue;           // mutual-pair symmetry break
                wf = __half2float(__ushort_as_half((unsigned short)(k32 >> 16)));
            } else {
                ull key = g_minER[r][c];
                if (key == ~0ull) continue;
                unsigned p = (unsigned)key;
                int a = (p >> 11) & 2047, b = p & 2047;
                int ra = (int)sroot16[a], rb = (int)sroot16[b];
                rd = (ra == c) ? rb : ra;
                bool skip = false;
                ull key2 = g_minER[r][rd];
                if (key2 != ~0ull) {
                    unsigned p2 = (unsigned)key2;
                    int a2 = (p2 >> 11) & 2047, b2 = p2 & 2047;
                    int ra2 = (int)sroot16[a2], rb2 = (int)sroot16[b2];
                    int tgt = (ra2 == rd) ? rb2 : ra2;
                    if (tgt == c && c > rd) skip = true;
                }
                if (skip) continue;
                wf = __uint_as_float((unsigned)(key >> 32));
            }
            parent16[c] = (unsigned short)rd;
            int idx = atomicAdd(&scnt, 1);
            if (bid == 0) g_edgeW[idx] = wf;
        }
        __syncthreads();
        if (scnt == N - 1) break;
    }
}

// ---------------- 4) warp-per-element rank sort ----------------
__global__ void rank_out_kernel(float* __restrict__ out) {
    __shared__ float sw[N];
    int tid  = threadIdx.x;
    int lane = tid & 31;
    int wrp  = tid >> 5;
    for (int j = tid; j < N; j += blockDim.x)
        sw[j] = (j < N - 1) ? g_edgeW[j] : 3.4028235e38f;
    __syncthreads();

    int i = blockIdx.x * 8 + wrp;
    if (i >= N - 1) return;
    float wi = sw[i];
    int rank = 0;
    const float4* sw4 = (const float4*)sw;
    #pragma unroll
    for (int q = lane; q < N / 4; q += 32) {
        float4 v = sw4[q];
        int j = q * 4;
        rank += (v.x < wi || (v.x == wi && j     < i));
        rank += (v.y < wi || (v.y == wi && j + 1 < i));
        rank += (v.z < wi || (v.z == wi && j + 2 < i));
        rank += (v.w < wi || (v.w == wi && j + 3 < i));
    }
    #pragma unroll
    for (int o = 16; o > 0; o >>= 1)
        rank += __shfl_down_sync(0xffffffffu, rank, o);
    if (lane == 0) out[rank] = wi;
}

// ---------------- launch ----------------
extern "C" void kernel_launch(void* const* d_in, const int* in_sizes, int n_in,
                              void* d_out, int out_size) {
    const float* x = (const float*)d_in[0];
    float* out = (float*)d_out;

    prep_kernel<<<N, 256>>>(x);

    static const int SMEM_SZ = STAGES * STAGE_BYTES + 1024;   // ~197KB
    cudaFuncSetAttribute(gemm_dist_kernel,
                         cudaFuncAttributeMaxDynamicSharedMemorySize, SMEM_SZ);
    gemm_dist_kernel<<<NTILES, 256, SMEM_SZ>>>();

    mst_kernel<<<MBLKS, MTHR>>>();
    rank_out_kernel<<<256, 256>>>(out);
}